// round 10
// baseline (speedup 1.0000x reference)
#include <cuda_runtime.h>
#include <cstring>

#define BB   8
#define CIN  8
#define COUT 16
#define HH   256
#define WW   256
#define HW   (HH * WW)          // 65536
#define NPIX (BB * HW)          // 524288
#define GROUPS_PER_IMG (HW / 4) // 16384 float4 pixel-groups per image
#define O_SPLIT 2
#define O_PER   (COUT / O_SPLIT) // 8 outputs per thread

__device__ __forceinline__ float ex2(float v) {
    float r;
    asm("ex2.approx.ftz.f32 %0, %1;" : "=f"(r) : "f"(v));
    return r;
}

// Packed f32x2 ops (Blackwell sm_103a)
__device__ __forceinline__ float2 add2(float2 a, float2 b) {
    unsigned long long ra, rb, rr;
    memcpy(&ra, &a, 8); memcpy(&rb, &b, 8);
    asm("add.rn.f32x2 %0, %1, %2;" : "=l"(rr) : "l"(ra), "l"(rb));
    float2 r; memcpy(&r, &rr, 8);
    return r;
}
__device__ __forceinline__ float2 fma2(float2 a, float2 b, float2 c) {
    unsigned long long ra, rb, rc, rr;
    memcpy(&ra, &a, 8); memcpy(&rb, &b, 8); memcpy(&rc, &c, 8);
    asm("fma.rn.f32x2 %0, %1, %2, %3;" : "=l"(rr) : "l"(ra), "l"(rb), "l"(rc));
    float2 r; memcpy(&r, &rr, 8);
    return r;
}

// FMA-pipe exp2, SCALAR Horner with immediate coefficients (FFMA-imm, rt=1):
// 4 independent chains per quad for ILP; no constant registers.
__device__ __forceinline__ float exp2_fma_s(float g) {
    float gc = fmaxf(g, -126.0f);              // alu FMNMX (imm)
    float t  = gc + 12582912.0f;               // rint in low mantissa bits
    float tm = t - 12582912.0f;                // rint(gc)
    float f  = gc - tm;                        // frac in [-0.5, 0.5]
    float p  = fmaf(f, 0.0013333558146429f, 0.0096181291076285f);
    p = fmaf(p, f, 0.0555041086648216f);
    p = fmaf(p, f, 0.2402265069591007f);
    p = fmaf(p, f, 0.6931471805599453f);
    p = fmaf(p, f, 1.0f);
    unsigned s = __float_as_uint(t) << 23;     // i << 23 (alu SHF+IADD)
    return __uint_as_float(__float_as_uint(p) + s);
}

__global__ __launch_bounds__(128) void rbf_hist_kernel(
    const float* __restrict__ x,
    const float* __restrict__ centers,
    const float* __restrict__ widths,
    float* __restrict__ out)
{
    // Exponent in log2 domain, FMA form: g = (A*x + B)*x + C
    //   A = -log2e/(2w^2), B = -2Ac, C = A c^2  (rel_err ~4e-7 path, verified)
    __shared__ float4 s_ab[COUT * CIN];   // (A, A, B, B)
    __shared__ float2 s_c[COUT * CIN];    // (C, C)

    int tid = threadIdx.x;
    if (tid < COUT * CIN) {
        float c = centers[tid];
        float w = widths[tid];
        float A = -1.44269504088896340736f / (2.0f * w * w);
        float Bv = -2.0f * A * c;
        float Cv = A * c * c;
        s_ab[tid] = make_float4(A, A, Bv, Bv);
        s_c[tid]  = make_float2(Cv, Cv);
    }
    __syncthreads();

    int idx = blockIdx.x * blockDim.x + tid;    // pixel-group id
    int b   = idx >> 14;
    int p4  = idx & (GROUPS_PER_IMG - 1);
    const float* xp = x + b * CIN * HW + p4 * 4;
    int obase = b * COUT * HW + p4 * 4;
    int o0  = blockIdx.y * O_PER;

    float2 xa[CIN], xb[CIN];
    #pragma unroll
    for (int j = 0; j < CIN; j++) {
        float4 v = *reinterpret_cast<const float4*>(xp + j * HW);
        xa[j] = make_float2(v.x, v.y);
        xb[j] = make_float2(v.z, v.w);
    }

    #pragma unroll
    for (int oo = 0; oo < O_PER; oo++) {
        int o = o0 + oo;
        const bool poly = (oo == 1) || (oo == 5);   // 2 of 8 outputs on FMA pipe
        float2 accA = make_float2(0.f, 0.f);
        float2 accB = make_float2(0.f, 0.f);
        #pragma unroll
        for (int j = 0; j < CIN; j++) {
            float4 ab = s_ab[o * CIN + j];
            float2 A  = make_float2(ab.x, ab.y);
            float2 Bv = make_float2(ab.z, ab.w);
            float2 Cv = s_c[o * CIN + j];
            float2 gA = fma2(fma2(A, xa[j], Bv), xa[j], Cv);
            float2 gB = fma2(fma2(A, xb[j], Bv), xb[j], Cv);
            if (poly) {
                accA = add2(accA, make_float2(exp2_fma_s(gA.x), exp2_fma_s(gA.y)));
                accB = add2(accB, make_float2(exp2_fma_s(gB.x), exp2_fma_s(gB.y)));
            } else {
                accA = add2(accA, make_float2(ex2(gA.x), ex2(gA.y)));
                accB = add2(accB, make_float2(ex2(gB.x), ex2(gB.y)));
            }
        }
        float4 r = make_float4(accA.x, accA.y, accB.x, accB.y);
        *reinterpret_cast<float4*>(out + obase + o * HW) = r;
    }
}

extern "C" void kernel_launch(void* const* d_in, const int* in_sizes, int n_in,
                              void* d_out, int out_size)
{
    const float* x       = (const float*)d_in[0];
    const float* centers = (const float*)d_in[1];
    const float* widths  = (const float*)d_in[2];
    float* out           = (float*)d_out;

    const int threads = 128;
    const int groups  = NPIX / 4;                  // 131072 pixel-group threads
    dim3 grid(groups / threads, O_SPLIT);          // (1024, 2)
    rbf_hist_kernel<<<grid, threads>>>(x, centers, widths, out);
}

// round 11
// speedup vs baseline: 1.2605x; 1.2605x over previous
#include <cuda_runtime.h>
#include <cstring>

#define BB   8
#define CIN  8
#define COUT 16
#define HH   256
#define WW   256
#define HW   (HH * WW)          // 65536
#define NPIX (BB * HW)          // 524288
#define GROUPS_PER_IMG (HW / 4) // 16384 float4 pixel-groups per image
#define O_SPLIT 2
#define O_PER   (COUT / O_SPLIT) // 8 outputs per thread

__device__ __forceinline__ float ex2(float v) {
    float r;
    asm("ex2.approx.ftz.f32 %0, %1;" : "=f"(r) : "f"(v));
    return r;
}

// Packed f32x2 ops (Blackwell sm_103a)
__device__ __forceinline__ float2 add2(float2 a, float2 b) {
    unsigned long long ra, rb, rr;
    memcpy(&ra, &a, 8); memcpy(&rb, &b, 8);
    asm("add.rn.f32x2 %0, %1, %2;" : "=l"(rr) : "l"(ra), "l"(rb));
    float2 r; memcpy(&r, &rr, 8);
    return r;
}
__device__ __forceinline__ float2 fma2(float2 a, float2 b, float2 c) {
    unsigned long long ra, rb, rc, rr;
    memcpy(&ra, &a, 8); memcpy(&rb, &b, 8); memcpy(&rc, &c, 8);
    asm("fma.rn.f32x2 %0, %1, %2, %3;" : "=l"(rr) : "l"(ra), "l"(rb), "l"(rc));
    float2 r; memcpy(&r, &rr, 8);
    return r;
}

__global__ __launch_bounds__(128) void rbf_hist_kernel(
    const float* __restrict__ x,
    const float* __restrict__ centers,
    const float* __restrict__ widths,
    float* __restrict__ out)
{
    // Exponent in log2 domain as FMA form: g = (A*x + B)*x + C
    //   A = -log2e/(2w^2), B = -2Ac, C = A c^2   (rel_err ~4e-7 verified)
    __shared__ float4 s_ab[COUT * CIN];   // (A, A, B, B)
    __shared__ float2 s_c[COUT * CIN];    // (C, C)

    int tid = threadIdx.x;
    if (tid < COUT * CIN) {
        float c = centers[tid];
        float w = widths[tid];
        float A = -1.44269504088896340736f / (2.0f * w * w);
        float Bv = -2.0f * A * c;
        float Cv = A * c * c;
        s_ab[tid] = make_float4(A, A, Bv, Bv);
        s_c[tid]  = make_float2(Cv, Cv);
    }
    __syncthreads();

    int idx = blockIdx.x * blockDim.x + tid;    // pixel-group id
    int b   = idx >> 14;
    int p4  = idx & (GROUPS_PER_IMG - 1);
    int xbase = b * CIN * HW + p4 * 4;
    int obase = b * COUT * HW + p4 * 4;
    int o0  = blockIdx.y * O_PER;               // this thread's output half

    float2 xa[CIN], xb[CIN];
    #pragma unroll
    for (int j = 0; j < CIN; j++) {
        float4 v = *reinterpret_cast<const float4*>(x + xbase + j * HW);
        xa[j] = make_float2(v.x, v.y);
        xb[j] = make_float2(v.z, v.w);
    }

    #pragma unroll
    for (int oo = 0; oo < O_PER; oo++) {
        int o = o0 + oo;
        float2 accA = make_float2(0.f, 0.f);
        float2 accB = make_float2(0.f, 0.f);
        #pragma unroll
        for (int j = 0; j < CIN; j++) {
            float4 ab = s_ab[o * CIN + j];
            float2 A  = make_float2(ab.x, ab.y);
            float2 Bv = make_float2(ab.z, ab.w);
            float2 Cv = s_c[o * CIN + j];
            float2 gA = fma2(fma2(A, xa[j], Bv), xa[j], Cv);
            float2 gB = fma2(fma2(A, xb[j], Bv), xb[j], Cv);
            accA = add2(accA, make_float2(ex2(gA.x), ex2(gA.y)));
            accB = add2(accB, make_float2(ex2(gB.x), ex2(gB.y)));
        }
        float4 r = make_float4(accA.x, accA.y, accB.x, accB.y);
        *reinterpret_cast<float4*>(out + obase + o * HW) = r;
    }
}

extern "C" void kernel_launch(void* const* d_in, const int* in_sizes, int n_in,
                              void* d_out, int out_size)
{
    const float* x       = (const float*)d_in[0];
    const float* centers = (const float*)d_in[1];
    const float* widths  = (const float*)d_in[2];
    float* out           = (float*)d_out;

    const int threads = 128;
    const int groups  = NPIX / 4;                  // 131072 pixel-group threads
    dim3 grid(groups / threads, O_SPLIT);          // (1024, 2)
    rbf_hist_kernel<<<grid, threads>>>(x, centers, widths, out);
}